// round 1
// baseline (speedup 1.0000x reference)
#include <cuda_runtime.h>
#include <math.h>

#define N_PAT 4096
#define DIM   256
#define KTOT  1024        // 4 modalities * 256 concatenated
#define EPSV  1e-8f

#define BM 128
#define BN 128
#define BK 16
#define NTB (N_PAT / BM)                 // 32 tiles per dim
#define NBLK_TRI (NTB * (NTB + 1) / 2)   // 528 upper-triangular tiles

// ---------------- static scratch (no allocations allowed) ----------------
__device__ float g_Xn[N_PAT * KTOT];      // normalized, miss-zeroed, concat-K
__device__ float4 g_a4[N_PAT];            // per-row: (!miss)*diag  for 4 mods
__device__ float4 g_nm4[N_PAT];           // per-row: (!miss)?1:0   for 4 mods
__device__ float g_exph[N_PAT];
__device__ float g_coxpart[N_PAT];
__device__ float g_blocksum[NBLK_TRI];

// ---------------- prep: one warp per (row, modality) ----------------
__global__ void prep_kernel(const float* __restrict__ eb0, const float* __restrict__ eb1,
                            const float* __restrict__ eb2, const float* __restrict__ eb3) {
    int gw = (blockIdx.x * blockDim.x + threadIdx.x) >> 5;
    int lane = threadIdx.x & 31;
    if (gw >= N_PAT * 4) return;
    int row = gw >> 2;
    int m = gw & 3;
    const float* base = (m == 0) ? eb0 : (m == 1) ? eb1 : (m == 2) ? eb2 : eb3;
    const float4* src = (const float4*)(base + (size_t)row * DIM);
    float4 v0 = src[lane];
    float4 v1 = src[lane + 32];

    // missing = all elements equal to element 0 (constant row)
    float x0 = __shfl_sync(0xffffffffu, v0.x, 0);
    bool eq = (v0.x == x0) && (v0.y == x0) && (v0.z == x0) && (v0.w == x0) &&
              (v1.x == x0) && (v1.y == x0) && (v1.z == x0) && (v1.w == x0);
    unsigned bal = __ballot_sync(0xffffffffu, eq);
    bool miss = (bal == 0xffffffffu);

    float ss = v0.x*v0.x + v0.y*v0.y + v0.z*v0.z + v0.w*v0.w
             + v1.x*v1.x + v1.y*v1.y + v1.z*v1.z + v1.w*v1.w;
#pragma unroll
    for (int o = 16; o > 0; o >>= 1) ss += __shfl_xor_sync(0xffffffffu, ss, o);

    float nrm = sqrtf(ss);
    float den = fmaxf(nrm, EPSV);
    float inv = miss ? 0.0f : (1.0f / den);

    float4* dst = (float4*)(g_Xn + (size_t)row * KTOT + m * DIM);
    dst[lane]      = make_float4(v0.x*inv, v0.y*inv, v0.z*inv, v0.w*inv);
    dst[lane + 32] = make_float4(v1.x*inv, v1.y*inv, v1.z*inv, v1.w*inv);

    if (lane == 0) {
        ((float*)g_a4)[row * 4 + m]  = miss ? 0.0f : (ss / (den * den)); // cos(x_i,x_i)
        ((float*)g_nm4)[row * 4 + m] = miss ? 0.0f : 1.0f;
    }
}

// ---------------- cox: exp(h) ----------------
__global__ void exph_kernel(const float* __restrict__ h) {
    int i = blockIdx.x * blockDim.x + threadIdx.x;
    if (i < N_PAT) g_exph[i] = expf(h[i]);
}

// ---------------- cox: per-row risk-set denominator (deterministic) ----------------
__global__ void cox_kernel(const float* __restrict__ h, const int* __restrict__ t,
                           const int* __restrict__ e) {
    __shared__ float sm[128];
    int i = blockIdx.x;
    int ti = t[i];
    float s = 0.0f;
    for (int j = threadIdx.x; j < N_PAT; j += 128) {
        // risk[i,j] = (t_i*t_j >= t_i^2)  <=>  t_i==0 || t_j>=t_i  (t>=0)
        if (ti == 0 || t[j] >= ti) s += g_exph[j];
    }
    sm[threadIdx.x] = s;
    __syncthreads();
#pragma unroll
    for (int o = 64; o > 0; o >>= 1) {
        if (threadIdx.x < o) sm[threadIdx.x] += sm[threadIdx.x + o];
        __syncthreads();
    }
    if (threadIdx.x == 0)
        g_coxpart[i] = e[i] ? (h[i] - logf(sm[0])) : 0.0f;
}

// ---------------- similarity GEMM: symmetric upper-triangular tiles ----------------
__global__ void __launch_bounds__(256) sim_gemm_kernel(const int* __restrict__ mptr) {
    // decode linear block index -> (bi <= bj)
    int L = blockIdx.x;
    int bi = 0;
    while (L >= (NTB - bi)) { L -= (NTB - bi); bi++; }
    int bj = bi + L;

    __shared__ __align__(16) float As[BK][BM + 4];
    __shared__ __align__(16) float Bs[BK][BN + 4];

    int tid = threadIdx.x;
    int tx = tid & 15;   // column micro-tile
    int ty = tid >> 4;   // row micro-tile

    float acc[8][8];
#pragma unroll
    for (int r = 0; r < 8; r++)
#pragma unroll
        for (int c = 0; c < 8; c++) acc[r][c] = 0.0f;

    const float* Aglob = g_Xn + (size_t)bi * BM * KTOT;
    const float* Bglob = g_Xn + (size_t)bj * BN * KTOT;

    for (int k0 = 0; k0 < KTOT; k0 += BK) {
#pragma unroll
        for (int l = 0; l < 2; l++) {
            int f = tid + l * 256;     // 0..511 : 512 float4 loads per tile
            int r = f >> 2;            // row within tile
            int c4 = f & 3;            // which float4 along k
            float4 va = *(const float4*)(Aglob + (size_t)r * KTOT + k0 + c4 * 4);
            As[c4 * 4 + 0][r] = va.x; As[c4 * 4 + 1][r] = va.y;
            As[c4 * 4 + 2][r] = va.z; As[c4 * 4 + 3][r] = va.w;
            float4 vb = *(const float4*)(Bglob + (size_t)r * KTOT + k0 + c4 * 4);
            Bs[c4 * 4 + 0][r] = vb.x; Bs[c4 * 4 + 1][r] = vb.y;
            Bs[c4 * 4 + 2][r] = vb.z; Bs[c4 * 4 + 3][r] = vb.w;
        }
        __syncthreads();
#pragma unroll
        for (int kk = 0; kk < BK; kk++) {
            float4 a0 = *(const float4*)&As[kk][ty * 8];
            float4 a1 = *(const float4*)&As[kk][ty * 8 + 4];
            float4 b0 = *(const float4*)&Bs[kk][tx * 8];
            float4 b1 = *(const float4*)&Bs[kk][tx * 8 + 4];
            float ar[8] = {a0.x, a0.y, a0.z, a0.w, a1.x, a1.y, a1.z, a1.w};
            float br[8] = {b0.x, b0.y, b0.z, b0.w, b1.x, b1.y, b1.z, b1.w};
#pragma unroll
            for (int r = 0; r < 8; r++)
#pragma unroll
                for (int c = 0; c < 8; c++) acc[r][c] += ar[r] * br[c];
        }
        __syncthreads();
    }

    // decode margin (int32 / int64-low-word / float32 safe)
    float margin;
    {
        int iv = mptr[0];
        margin = (iv > -1000000 && iv < 1000000) ? (float)iv : __int_as_float(iv);
    }

    // stage rank-4 correction vectors in shared (reuse As)
    float* sa_i  = (float*)As;           // a  for rows i   (512 floats)
    float* snm_j = sa_i + 512;           // nm for cols j
    float* sa_j  = snm_j + 512;          // a  for cols j
    float* snm_i = sa_j + 512;           // nm for rows i
    int i0 = bi * BM, j0 = bj * BN;
    if (tid < 128) {
        *(float4*)&sa_i [tid * 4] = g_a4 [i0 + tid];
        *(float4*)&snm_j[tid * 4] = g_nm4[j0 + tid];
        *(float4*)&sa_j [tid * 4] = g_a4 [j0 + tid];
        *(float4*)&snm_i[tid * 4] = g_nm4[i0 + tid];
    }
    __syncthreads();

    float sum = 0.0f;
#pragma unroll
    for (int r = 0; r < 8; r++) {
        int li = ty * 8 + r;
        float4 ai = *(const float4*)&sa_i[li * 4];
        float4 ni = *(const float4*)&snm_i[li * 4];
        int gi = i0 + li;
#pragma unroll
        for (int c = 0; c < 8; c++) {
            int lj = tx * 8 + c;
            float4 nj = *(const float4*)&snm_j[lj * 4];
            float s_ij = acc[r][c];
            // per_pair[i,j] = relu(margin - matched + own[i,j]), own = a_i . nm_j
            float corr = ai.x * nj.x + ai.y * nj.y + ai.z * nj.z + ai.w * nj.w;
            int gj = j0 + lj;
            if (gi != gj) sum += fmaxf(margin - s_ij + corr, 0.0f);
            if (bi != bj) {
                float4 aj = *(const float4*)&sa_j[lj * 4];
                float corr2 = aj.x * ni.x + aj.y * ni.y + aj.z * ni.z + aj.w * ni.w;
                sum += fmaxf(margin - s_ij + corr2, 0.0f);   // per_pair[j,i]
            }
        }
    }

    __shared__ float red[256];
    red[tid] = sum;
    __syncthreads();
#pragma unroll
    for (int o = 128; o > 0; o >>= 1) {
        if (tid < o) red[tid] += red[tid + o];
        __syncthreads();
    }
    if (tid == 0) g_blocksum[blockIdx.x] = red[0];
}

// ---------------- final deterministic reduction ----------------
__global__ void finish_kernel(const int* __restrict__ e, float* __restrict__ out) {
    __shared__ float sm[256];
    int tid = threadIdx.x;

    float s = 0.0f;
    for (int b = tid; b < NBLK_TRI; b += 256) s += g_blocksum[b];
    sm[tid] = s; __syncthreads();
#pragma unroll
    for (int o = 128; o > 0; o >>= 1) { if (tid < o) sm[tid] += sm[tid + o]; __syncthreads(); }
    float sim = sm[0]; __syncthreads();

    float cp = 0.0f;
    for (int i = tid; i < N_PAT; i += 256) cp += g_coxpart[i];
    sm[tid] = cp; __syncthreads();
#pragma unroll
    for (int o = 128; o > 0; o >>= 1) { if (tid < o) sm[tid] += sm[tid + o]; __syncthreads(); }
    float cox = sm[0]; __syncthreads();

    float ef = 0.0f;
    for (int i = tid; i < N_PAT; i += 256) ef += (float)e[i];
    sm[tid] = ef; __syncthreads();
#pragma unroll
    for (int o = 128; o > 0; o >>= 1) { if (tid < o) sm[tid] += sm[tid + o]; __syncthreads(); }

    if (tid == 0) out[0] = sim - cox / sm[0];
}

// ---------------- launch ----------------
extern "C" void kernel_launch(void* const* d_in, const int* in_sizes, int n_in,
                              void* d_out, int out_size) {
    const float* h   = (const float*)d_in[0];
    const int*   t   = (const int*)d_in[1];
    const int*   e   = (const int*)d_in[2];
    const float* eb0 = (const float*)d_in[3];
    const float* eb1 = (const float*)d_in[4];
    const float* eb2 = (const float*)d_in[5];
    const float* eb3 = (const float*)d_in[6];
    const int*   mg  = (const int*)d_in[7];
    float* out = (float*)d_out;

    prep_kernel<<<(N_PAT * 4 * 32 + 255) / 256, 256>>>(eb0, eb1, eb2, eb3);
    exph_kernel<<<(N_PAT + 255) / 256, 256>>>(h);
    cox_kernel<<<N_PAT, 128>>>(h, t, e);
    sim_gemm_kernel<<<NBLK_TRI, 256>>>(mg);
    finish_kernel<<<1, 256>>>(e, out);
}

// round 3
// speedup vs baseline: 3.2506x; 3.2506x over previous
#include <cuda_runtime.h>
#include <cuda_bf16.h>
#include <math.h>
#include <stdint.h>

#define N_PAT 4096
#define DIM   256
#define KTOT  1024
#define EPSV  1e-8f

#define BM 128
#define BN 128
#define BK 64
#define NCHUNKS (KTOT / BK)              // 16
#define NTB (N_PAT / BM)                 // 32
#define NBLK_TRI (NTB * (NTB + 1) / 2)   // 528

#define ASTRIDE 72                       // elems per smem row (144B, conflict-free)
#define TILE_BYTES (128 * ASTRIDE * 2)   // 18432 per operand tile
#define STAGE_BYTES (2 * TILE_BYTES)     // A + B

// smem byte offsets
#define SM_VEC  (2 * STAGE_BYTES)        // 73728 : 4 arrays x 128 float4
#define SM_RED  (SM_VEC + 8192)          // 81920
#define SM_TOTAL (SM_RED + 1024)         // 82944

// ---------------- static scratch ----------------
__device__ __nv_bfloat16 g_Xb[N_PAT * KTOT];   // normalized, miss-zeroed bf16
__device__ float4 g_a4[N_PAT];
__device__ float4 g_nm4[N_PAT];
__device__ float g_exph[N_PAT];
__device__ float g_coxpart[N_PAT];
__device__ float g_blocksum[NBLK_TRI];

// ---------------- helpers ----------------
__device__ __forceinline__ uint32_t smem_u32(const void* p) {
    uint32_t a;
    asm("{ .reg .u64 t; cvta.to.shared.u64 t, %1; cvt.u32.u64 %0, t; }" : "=r"(a) : "l"(p));
    return a;
}
__device__ __forceinline__ void cp_async16(uint32_t saddr, const void* gaddr) {
    asm volatile("cp.async.cg.shared.global [%0], [%1], 16;" :: "r"(saddr), "l"(gaddr) : "memory");
}
__device__ __forceinline__ void ldmat_x4(uint32_t* r, uint32_t addr) {
    asm volatile("ldmatrix.sync.aligned.m8n8.x4.shared.b16 {%0,%1,%2,%3}, [%4];"
                 : "=r"(r[0]), "=r"(r[1]), "=r"(r[2]), "=r"(r[3]) : "r"(addr));
}
__device__ __forceinline__ void mma16816(float* d, const uint32_t* a, const uint32_t* b) {
    asm volatile(
        "mma.sync.aligned.m16n8k16.row.col.f32.bf16.bf16.f32 "
        "{%0,%1,%2,%3},{%4,%5,%6,%7},{%8,%9},{%0,%1,%2,%3};"
        : "+f"(d[0]), "+f"(d[1]), "+f"(d[2]), "+f"(d[3])
        : "r"(a[0]), "r"(a[1]), "r"(a[2]), "r"(a[3]), "r"(b[0]), "r"(b[1]));
}

// ---------------- prep: normalize + miss-mask + bf16 ----------------
__global__ void prep_kernel(const float* __restrict__ eb0, const float* __restrict__ eb1,
                            const float* __restrict__ eb2, const float* __restrict__ eb3) {
    int gw = (blockIdx.x * blockDim.x + threadIdx.x) >> 5;
    int lane = threadIdx.x & 31;
    if (gw >= N_PAT * 4) return;
    int row = gw >> 2;
    int m = gw & 3;
    const float* base = (m == 0) ? eb0 : (m == 1) ? eb1 : (m == 2) ? eb2 : eb3;
    const float4* src = (const float4*)(base + (size_t)row * DIM);
    float4 v0 = src[lane];
    float4 v1 = src[lane + 32];

    float x0 = __shfl_sync(0xffffffffu, v0.x, 0);
    bool eq = (v0.x == x0) && (v0.y == x0) && (v0.z == x0) && (v0.w == x0) &&
              (v1.x == x0) && (v1.y == x0) && (v1.z == x0) && (v1.w == x0);
    bool miss = (__ballot_sync(0xffffffffu, eq) == 0xffffffffu);

    float ss = v0.x*v0.x + v0.y*v0.y + v0.z*v0.z + v0.w*v0.w
             + v1.x*v1.x + v1.y*v1.y + v1.z*v1.z + v1.w*v1.w;
#pragma unroll
    for (int o = 16; o > 0; o >>= 1) ss += __shfl_xor_sync(0xffffffffu, ss, o);

    float nrm = sqrtf(ss);
    float den = fmaxf(nrm, EPSV);
    float inv = miss ? 0.0f : (1.0f / den);

    __nv_bfloat16* dst = g_Xb + (size_t)row * KTOT + m * DIM;
    __nv_bfloat162 p0 = __floats2bfloat162_rn(v0.x * inv, v0.y * inv);
    __nv_bfloat162 p1 = __floats2bfloat162_rn(v0.z * inv, v0.w * inv);
    __nv_bfloat162 p2 = __floats2bfloat162_rn(v1.x * inv, v1.y * inv);
    __nv_bfloat162 p3 = __floats2bfloat162_rn(v1.z * inv, v1.w * inv);
    uint2 u0 = make_uint2(*(uint32_t*)&p0, *(uint32_t*)&p1);
    uint2 u1 = make_uint2(*(uint32_t*)&p2, *(uint32_t*)&p3);
    *(uint2*)(dst + lane * 4) = u0;
    *(uint2*)(dst + 128 + lane * 4) = u1;

    if (lane == 0) {
        ((float*)g_a4)[row * 4 + m]  = miss ? 0.0f : (ss / (den * den));
        ((float*)g_nm4)[row * 4 + m] = miss ? 0.0f : 1.0f;
    }
}

// ---------------- cox ----------------
__global__ void exph_kernel(const float* __restrict__ h) {
    int i = blockIdx.x * blockDim.x + threadIdx.x;
    if (i < N_PAT) g_exph[i] = expf(h[i]);
}

// 32 rows per block, j tiled through shared memory
__global__ void cox_kernel(const float* __restrict__ h, const int* __restrict__ t,
                           const int* __restrict__ e) {
    __shared__ int st[1024];
    __shared__ float se[1024];
    int tid = threadIdx.x;
    int il = tid >> 3;        // 0..31 local row
    int sub = tid & 7;
    int i = blockIdx.x * 32 + il;
    int ti = t[i];
    float s = 0.0f;
    for (int j0 = 0; j0 < N_PAT; j0 += 1024) {
        __syncthreads();
        for (int j = tid; j < 1024; j += 256) { st[j] = t[j0 + j]; se[j] = g_exph[j0 + j]; }
        __syncthreads();
#pragma unroll 4
        for (int j = sub; j < 1024; j += 8)
            if (ti == 0 || st[j] >= ti) s += se[j];
    }
#pragma unroll
    for (int o = 4; o > 0; o >>= 1) s += __shfl_xor_sync(0xffffffffu, s, o);
    if (sub == 0)
        g_coxpart[i] = e[i] ? (h[i] - logf(s)) : 0.0f;
}

// ---------------- bf16 tensor-core GEMM over upper-triangular tiles ----------------
__global__ void __launch_bounds__(256, 2)
sim_gemm_mma(const int* __restrict__ mptr) {
    extern __shared__ __align__(1024) char smem[];
    uint32_t sb = smem_u32(smem);
    int tid = threadIdx.x;
    int wid = tid >> 5;
    int lane = tid & 31;

    // triangular tile decode
    int L = blockIdx.x, bi = 0;
    while (L >= (NTB - bi)) { L -= (NTB - bi); bi++; }
    int bj = bi + L;
    int i0 = bi * BM, j0 = bj * BN;

    // rank-4 correction vectors
    float4* sa_i  = (float4*)(smem + SM_VEC);
    float4* snm_i = sa_i + 128;
    float4* sa_j  = snm_i + 128;
    float4* snm_j = sa_j + 128;
    if (tid < 128) {
        sa_i[tid]  = g_a4[i0 + tid];
        snm_i[tid] = g_nm4[i0 + tid];
        sa_j[tid]  = g_a4[j0 + tid];
        snm_j[tid] = g_nm4[j0 + tid];
    }

    const __nv_bfloat16* Abase = g_Xb + (size_t)i0 * KTOT;
    const __nv_bfloat16* Bbase = g_Xb + (size_t)j0 * KTOT;

    // per-thread cp.async mapping: 4 segs A + 4 segs B per chunk
    int row_ld[4], sc_ld;
    sc_ld = tid & 7;
#pragma unroll
    for (int p = 0; p < 4; p++) row_ld[p] = ((tid + p * 256) >> 3);

    // issue chunk 0
#pragma unroll
    for (int p = 0; p < 4; p++) {
        int r = row_ld[p];
        cp_async16(sb + r * 144 + sc_ld * 16,
                   Abase + (size_t)r * KTOT + sc_ld * 8);
        cp_async16(sb + TILE_BYTES + r * 144 + sc_ld * 16,
                   Bbase + (size_t)r * KTOT + sc_ld * 8);
    }
    asm volatile("cp.async.commit_group;" ::: "memory");

    // warp tiling: 2 (m) x 4 (n)
    int wm = wid >> 2;          // 0..1
    int wn = wid & 3;           // 0..3

    float acc[4][4][4];
#pragma unroll
    for (int a = 0; a < 4; a++)
#pragma unroll
        for (int b = 0; b < 4; b++)
#pragma unroll
            for (int c = 0; c < 4; c++) acc[a][b][c] = 0.0f;

    // ldmatrix lane address components (same formula for A and B x4 tiles)
    int lrow = lane & 15;
    int lcol = (lane >> 4) << 3;   // 0 or 8 elems

#pragma unroll 1
    for (int c = 0; c < NCHUNKS; c++) {
        int s = c & 1;
        if (c + 1 < NCHUNKS) {
            int snx = (c + 1) & 1;
            int k0 = (c + 1) * BK;
#pragma unroll
            for (int p = 0; p < 4; p++) {
                int r = row_ld[p];
                cp_async16(sb + snx * STAGE_BYTES + r * 144 + sc_ld * 16,
                           Abase + (size_t)r * KTOT + k0 + sc_ld * 8);
                cp_async16(sb + snx * STAGE_BYTES + TILE_BYTES + r * 144 + sc_ld * 16,
                           Bbase + (size_t)r * KTOT + k0 + sc_ld * 8);
            }
            asm volatile("cp.async.commit_group;" ::: "memory");
            asm volatile("cp.async.wait_group 1;" ::: "memory");
        } else {
            asm volatile("cp.async.wait_group 0;" ::: "memory");
        }
        __syncthreads();

        uint32_t aSt = sb + s * STAGE_BYTES;
        uint32_t bSt = aSt + TILE_BYTES;
#pragma unroll
        for (int ks = 0; ks < 4; ks++) {
            uint32_t af[4][4];
            uint32_t bf[2][4];
#pragma unroll
            for (int mf = 0; mf < 4; mf++) {
                uint32_t addr = aSt + ((wm * 64 + mf * 16 + lrow) * ASTRIDE + ks * 16 + lcol) * 2;
                ldmat_x4(af[mf], addr);
            }
#pragma unroll
            for (int nfp = 0; nfp < 2; nfp++) {
                uint32_t addr = bSt + ((wn * 32 + nfp * 16 + lrow) * ASTRIDE + ks * 16 + lcol) * 2;
                ldmat_x4(bf[nfp], addr);
            }
#pragma unroll
            for (int mf = 0; mf < 4; mf++) {
#pragma unroll
                for (int nf = 0; nf < 4; nf++) {
                    uint32_t bb[2] = { bf[nf >> 1][nf & 1], bf[nf >> 1][(nf & 1) + 2] };
                    mma16816(acc[mf][nf], af[mf], bb);
                }
            }
        }
        __syncthreads();
    }

    // margin decode (int32 / float32 bit-safe)
    float margin;
    {
        int iv = mptr[0];
        margin = (iv > -1000000 && iv < 1000000) ? (float)iv : __int_as_float(iv);
    }

    // epilogue: rank-4 correction + relu + sum (both orientations)
    float sum = 0.0f;
    int qrow = lane >> 2;          // 0..7
    int qcol = (lane & 3) * 2;     // 0,2,4,6
#pragma unroll
    for (int mf = 0; mf < 4; mf++) {
#pragma unroll
        for (int half = 0; half < 2; half++) {      // regs 0,1 vs 2,3 (row +8)
            int li = wm * 64 + mf * 16 + qrow + half * 8;
            int gi = i0 + li;
            float4 ai = sa_i[li];
            float4 ni = snm_i[li];
#pragma unroll
            for (int nf = 0; nf < 4; nf++) {
#pragma unroll
                for (int rg = 0; rg < 2; rg++) {    // col +0 / +1
                    int lj = wn * 32 + nf * 8 + qcol + rg;
                    float sv = acc[mf][nf][half * 2 + rg];
                    float4 nj = snm_j[lj];
                    float corr = ai.x * nj.x + ai.y * nj.y + ai.z * nj.z + ai.w * nj.w;
                    if (gi != j0 + lj) sum += fmaxf(margin - sv + corr, 0.0f);
                    if (bi != bj) {
                        float4 aj = sa_j[lj];
                        float4 nif = ni;
                        float corr2 = aj.x * nif.x + aj.y * nif.y + aj.z * nif.z + aj.w * nif.w;
                        sum += fmaxf(margin - sv + corr2, 0.0f);
                    }
                }
            }
        }
    }

    float* red = (float*)(smem + SM_RED);
    red[tid] = sum;
    __syncthreads();
#pragma unroll
    for (int o = 128; o > 0; o >>= 1) {
        if (tid < o) red[tid] += red[tid + o];
        __syncthreads();
    }
    if (tid == 0) g_blocksum[blockIdx.x] = red[0];
}

// ---------------- final deterministic reduction ----------------
__global__ void finish_kernel(const int* __restrict__ e, float* __restrict__ out) {
    __shared__ float sm[256];
    int tid = threadIdx.x;

    float s = 0.0f;
    for (int b = tid; b < NBLK_TRI; b += 256) s += g_blocksum[b];
    sm[tid] = s; __syncthreads();
#pragma unroll
    for (int o = 128; o > 0; o >>= 1) { if (tid < o) sm[tid] += sm[tid + o]; __syncthreads(); }
    float sim = sm[0]; __syncthreads();

    float cp = 0.0f;
    for (int i = tid; i < N_PAT; i += 256) cp += g_coxpart[i];
    sm[tid] = cp; __syncthreads();
#pragma unroll
    for (int o = 128; o > 0; o >>= 1) { if (tid < o) sm[tid] += sm[tid + o]; __syncthreads(); }
    float cox = sm[0]; __syncthreads();

    float ef = 0.0f;
    for (int i = tid; i < N_PAT; i += 256) ef += (float)e[i];
    sm[tid] = ef; __syncthreads();
#pragma unroll
    for (int o = 128; o > 0; o >>= 1) { if (tid < o) sm[tid] += sm[tid + o]; __syncthreads(); }

    if (tid == 0) out[0] = sim - cox / sm[0];
}

// ---------------- launch ----------------
extern "C" void kernel_launch(void* const* d_in, const int* in_sizes, int n_in,
                              void* d_out, int out_size) {
    const float* h   = (const float*)d_in[0];
    const int*   t   = (const int*)d_in[1];
    const int*   e   = (const int*)d_in[2];
    const float* eb0 = (const float*)d_in[3];
    const float* eb1 = (const float*)d_in[4];
    const float* eb2 = (const float*)d_in[5];
    const float* eb3 = (const float*)d_in[6];
    const int*   mg  = (const int*)d_in[7];
    float* out = (float*)d_out;

    cudaFuncSetAttribute(sim_gemm_mma, cudaFuncAttributeMaxDynamicSharedMemorySize, SM_TOTAL);

    prep_kernel<<<(N_PAT * 4 * 32 + 255) / 256, 256>>>(eb0, eb1, eb2, eb3);
    exph_kernel<<<(N_PAT + 255) / 256, 256>>>(h);
    cox_kernel<<<N_PAT / 32, 256>>>(h, t, e);
    sim_gemm_mma<<<NBLK_TRI, 256, SM_TOTAL>>>(mg);
    finish_kernel<<<1, 256>>>(e, out);
}

// round 4
// speedup vs baseline: 3.5028x; 1.0776x over previous
#include <cuda_runtime.h>
#include <cuda_bf16.h>
#include <math.h>
#include <stdint.h>

#define N_PAT 4096
#define DIM   256
#define KTOT  1024
#define EPSV  1e-8f

#define BM 128
#define BN 128
#define BK 64
#define NCHUNKS (KTOT / BK)              // 16
#define NTB (N_PAT / BM)                 // 32
#define NBLK_TRI (NTB * (NTB + 1) / 2)   // 528

#define TILE_B   16384                   // 128 rows x 128B (swizzled, no pad)
#define STAGE_B  (2 * TILE_B)            // 32KB (A + B)
#define NSTAGE   3

#define SM_VEC  (NSTAGE * STAGE_B)       // 98304
#define SM_RED  (SM_VEC + 8192)          // 106496
#define SM_TOTAL (SM_RED + 512)          // 107008

// ---------------- static scratch ----------------
__device__ __nv_bfloat16 g_Xb[N_PAT * KTOT];
__device__ float4 g_a4[N_PAT];
__device__ float4 g_nm4[N_PAT];
__device__ float g_exph[N_PAT];
__device__ float g_coxpart[N_PAT];
__device__ float g_blocksum[NBLK_TRI];

// ---------------- helpers ----------------
__device__ __forceinline__ uint32_t smem_u32(const void* p) {
    uint32_t a;
    asm("{ .reg .u64 t; cvta.to.shared.u64 t, %1; cvt.u32.u64 %0, t; }" : "=r"(a) : "l"(p));
    return a;
}
__device__ __forceinline__ void cp_async16(uint32_t saddr, const void* gaddr) {
    asm volatile("cp.async.cg.shared.global [%0], [%1], 16;" :: "r"(saddr), "l"(gaddr) : "memory");
}
__device__ __forceinline__ void ldmat_x4(uint32_t* r, uint32_t addr) {
    asm volatile("ldmatrix.sync.aligned.m8n8.x4.shared.b16 {%0,%1,%2,%3}, [%4];"
                 : "=r"(r[0]), "=r"(r[1]), "=r"(r[2]), "=r"(r[3]) : "r"(addr));
}
__device__ __forceinline__ void mma16816(float* d, const uint32_t* a, uint32_t b0, uint32_t b1) {
    asm volatile(
        "mma.sync.aligned.m16n8k16.row.col.f32.bf16.bf16.f32 "
        "{%0,%1,%2,%3},{%4,%5,%6,%7},{%8,%9},{%0,%1,%2,%3};"
        : "+f"(d[0]), "+f"(d[1]), "+f"(d[2]), "+f"(d[3])
        : "r"(a[0]), "r"(a[1]), "r"(a[2]), "r"(a[3]), "r"(b0), "r"(b1));
}

// ---------------- prep: normalize + miss-mask + bf16 ----------------
__global__ void prep_kernel(const float* __restrict__ eb0, const float* __restrict__ eb1,
                            const float* __restrict__ eb2, const float* __restrict__ eb3) {
    int gw = (blockIdx.x * blockDim.x + threadIdx.x) >> 5;
    int lane = threadIdx.x & 31;
    if (gw >= N_PAT * 4) return;
    int row = gw >> 2;
    int m = gw & 3;
    const float* base = (m == 0) ? eb0 : (m == 1) ? eb1 : (m == 2) ? eb2 : eb3;
    const float4* src = (const float4*)(base + (size_t)row * DIM);
    float4 v0 = src[lane];
    float4 v1 = src[lane + 32];

    float x0 = __shfl_sync(0xffffffffu, v0.x, 0);
    bool eq = (v0.x == x0) && (v0.y == x0) && (v0.z == x0) && (v0.w == x0) &&
              (v1.x == x0) && (v1.y == x0) && (v1.z == x0) && (v1.w == x0);
    bool miss = (__ballot_sync(0xffffffffu, eq) == 0xffffffffu);

    float ss = v0.x*v0.x + v0.y*v0.y + v0.z*v0.z + v0.w*v0.w
             + v1.x*v1.x + v1.y*v1.y + v1.z*v1.z + v1.w*v1.w;
#pragma unroll
    for (int o = 16; o > 0; o >>= 1) ss += __shfl_xor_sync(0xffffffffu, ss, o);

    float nrm = sqrtf(ss);
    float den = fmaxf(nrm, EPSV);
    float inv = miss ? 0.0f : (1.0f / den);

    __nv_bfloat16* dst = g_Xb + (size_t)row * KTOT + m * DIM;
    __nv_bfloat162 p0 = __floats2bfloat162_rn(v0.x * inv, v0.y * inv);
    __nv_bfloat162 p1 = __floats2bfloat162_rn(v0.z * inv, v0.w * inv);
    __nv_bfloat162 p2 = __floats2bfloat162_rn(v1.x * inv, v1.y * inv);
    __nv_bfloat162 p3 = __floats2bfloat162_rn(v1.z * inv, v1.w * inv);
    uint2 u0 = make_uint2(*(uint32_t*)&p0, *(uint32_t*)&p1);
    uint2 u1 = make_uint2(*(uint32_t*)&p2, *(uint32_t*)&p3);
    *(uint2*)(dst + lane * 4) = u0;
    *(uint2*)(dst + 128 + lane * 4) = u1;

    if (lane == 0) {
        ((float*)g_a4)[row * 4 + m]  = miss ? 0.0f : (ss / (den * den));
        ((float*)g_nm4)[row * 4 + m] = miss ? 0.0f : 1.0f;
    }
}

// ---------------- cox ----------------
__global__ void exph_kernel(const float* __restrict__ h) {
    int i = blockIdx.x * blockDim.x + threadIdx.x;
    if (i < N_PAT) g_exph[i] = expf(h[i]);
}

__global__ void cox_kernel(const float* __restrict__ h, const int* __restrict__ t,
                           const int* __restrict__ e) {
    __shared__ int st[1024];
    __shared__ float se[1024];
    int tid = threadIdx.x;
    int il = tid >> 3;
    int sub = tid & 7;
    int i = blockIdx.x * 32 + il;
    int ti = t[i];
    float s = 0.0f;
    for (int j0 = 0; j0 < N_PAT; j0 += 1024) {
        __syncthreads();
        for (int j = tid; j < 1024; j += 256) { st[j] = t[j0 + j]; se[j] = g_exph[j0 + j]; }
        __syncthreads();
#pragma unroll 4
        for (int j = sub; j < 1024; j += 8)
            if (ti == 0 || st[j] >= ti) s += se[j];
    }
#pragma unroll
    for (int o = 4; o > 0; o >>= 1) s += __shfl_xor_sync(0xffffffffu, s, o);
    if (sub == 0)
        g_coxpart[i] = e[i] ? (h[i] - logf(s)) : 0.0f;
}

// ---------------- GEMM: 128 thr, 4 warps x (64x64), 3-stage swizzled ----------------
__device__ __forceinline__ void issue_chunk(uint32_t stage, const __nv_bfloat16* Ab,
                                            const __nv_bfloat16* Bb, int k0, int tid) {
#pragma unroll
    for (int p = 0; p < 8; p++) {
        int lin = p * 128 + tid;
        int r = lin >> 3, s = lin & 7;
        uint32_t off = (r << 7) + ((s ^ (r & 7)) << 4);
        const __nv_bfloat16* ga = Ab + (size_t)r * KTOT + k0 + s * 8;
        const __nv_bfloat16* gb = Bb + (size_t)r * KTOT + k0 + s * 8;
        cp_async16(stage + off, ga);
        cp_async16(stage + TILE_B + off, gb);
    }
    asm volatile("cp.async.commit_group;" ::: "memory");
}

__global__ void __launch_bounds__(128, 2)
sim_gemm_mma(const int* __restrict__ mptr) {
    extern __shared__ __align__(1024) char smem[];
    uint32_t sb = smem_u32(smem);
    int tid = threadIdx.x;
    int wid = tid >> 5;
    int lane = tid & 31;
    int wm = wid >> 1, wn = wid & 1;

    int L = blockIdx.x, bi = 0;
    while (L >= (NTB - bi)) { L -= (NTB - bi); bi++; }
    int bj = bi + L;
    int i0 = bi * BM, j0 = bj * BN;

    float4* sa_i  = (float4*)(smem + SM_VEC);
    float4* snm_i = sa_i + 128;
    float4* sa_j  = snm_i + 128;
    float4* snm_j = sa_j + 128;
    sa_i[tid]  = g_a4[i0 + tid];
    snm_i[tid] = g_nm4[i0 + tid];
    sa_j[tid]  = g_a4[j0 + tid];
    snm_j[tid] = g_nm4[j0 + tid];

    const __nv_bfloat16* Abase = g_Xb + (size_t)i0 * KTOT;
    const __nv_bfloat16* Bbase = g_Xb + (size_t)j0 * KTOT;

    // prologue: chunks 0,1
    issue_chunk(sb, Abase, Bbase, 0, tid);
    issue_chunk(sb + STAGE_B, Abase, Bbase, BK, tid);

    float acc[4][8][4];
#pragma unroll
    for (int a = 0; a < 4; a++)
#pragma unroll
        for (int b = 0; b < 8; b++)
#pragma unroll
            for (int c = 0; c < 4; c++) acc[a][b][c] = 0.0f;

    int lrow = lane & 15;
    int lhalf = lane >> 4;
    // swizzled unit byte-offset per ks (independent of fragment row-base)
    uint32_t uoff[4];
#pragma unroll
    for (int ks = 0; ks < 4; ks++)
        uoff[ks] = (uint32_t)(((ks * 2 + lhalf) ^ (lrow & 7)) << 4);
    uint32_t rowA = (uint32_t)(wm * 64 + lrow) << 7;   // byte row offset within A tile
    uint32_t rowB = (uint32_t)(wn * 64 + lrow) << 7;

#pragma unroll 1
    for (int c = 0; c < NCHUNKS; c++) {
        if (c < NCHUNKS - 1) asm volatile("cp.async.wait_group 1;" ::: "memory");
        else                 asm volatile("cp.async.wait_group 0;" ::: "memory");
        __syncthreads();
        if (c + 2 < NCHUNKS)
            issue_chunk(sb + ((c + 2) % NSTAGE) * STAGE_B, Abase, Bbase, (c + 2) * BK, tid);

        uint32_t stA = sb + (c % NSTAGE) * STAGE_B;
        uint32_t stB = stA + TILE_B;
#pragma unroll
        for (int ks = 0; ks < 4; ks++) {
            uint32_t af[4][4], bf[4][4];
#pragma unroll
            for (int mf = 0; mf < 4; mf++)
                ldmat_x4(af[mf], stA + rowA + (uint32_t)(mf << 11) + uoff[ks]);
#pragma unroll
            for (int nfp = 0; nfp < 4; nfp++)
                ldmat_x4(bf[nfp], stB + rowB + (uint32_t)(nfp << 11) + uoff[ks]);
#pragma unroll
            for (int mf = 0; mf < 4; mf++)
#pragma unroll
                for (int nf = 0; nf < 8; nf++)
                    mma16816(acc[mf][nf], af[mf], bf[nf >> 1][nf & 1], bf[nf >> 1][(nf & 1) + 2]);
        }
    }
    __syncthreads();

    float margin;
    {
        int iv = mptr[0];
        margin = (iv > -1000000 && iv < 1000000) ? (float)iv : __int_as_float(iv);
    }

    float sum = 0.0f;
    int qrow = lane >> 2;
    int qcol = (lane & 3) * 2;
#pragma unroll
    for (int mf = 0; mf < 4; mf++) {
#pragma unroll
        for (int half = 0; half < 2; half++) {
            int li = wm * 64 + mf * 16 + qrow + half * 8;
            int gi = i0 + li;
            float4 ai = sa_i[li];
            float4 ni = snm_i[li];
#pragma unroll
            for (int nf = 0; nf < 8; nf++) {
#pragma unroll
                for (int rg = 0; rg < 2; rg++) {
                    int lj = wn * 64 + nf * 8 + qcol + rg;
                    float sv = acc[mf][nf][half * 2 + rg];
                    float4 nj = snm_j[lj];
                    float corr = ai.x * nj.x + ai.y * nj.y + ai.z * nj.z + ai.w * nj.w;
                    if (gi != j0 + lj) sum += fmaxf(margin - sv + corr, 0.0f);
                    if (bi != bj) {
                        float4 aj = sa_j[lj];
                        float corr2 = aj.x * ni.x + aj.y * ni.y + aj.z * ni.z + aj.w * ni.w;
                        sum += fmaxf(margin - sv + corr2, 0.0f);
                    }
                }
            }
        }
    }

    float* red = (float*)(smem + SM_RED);
    red[tid] = sum;
    __syncthreads();
#pragma unroll
    for (int o = 64; o > 0; o >>= 1) {
        if (tid < o) red[tid] += red[tid + o];
        __syncthreads();
    }
    if (tid == 0) g_blocksum[blockIdx.x] = red[0];
}

// ---------------- final deterministic reduction ----------------
__global__ void finish_kernel(const int* __restrict__ e, float* __restrict__ out) {
    __shared__ float sm[1024];
    int tid = threadIdx.x;

    float s = 0.0f;
    for (int b = tid; b < NBLK_TRI; b += 1024) s += g_blocksum[b];
    sm[tid] = s; __syncthreads();
#pragma unroll
    for (int o = 512; o > 0; o >>= 1) { if (tid < o) sm[tid] += sm[tid + o]; __syncthreads(); }
    float sim = sm[0]; __syncthreads();

    float cp = 0.0f;
    for (int i = tid; i < N_PAT; i += 1024) cp += g_coxpart[i];
    sm[tid] = cp; __syncthreads();
#pragma unroll
    for (int o = 512; o > 0; o >>= 1) { if (tid < o) sm[tid] += sm[tid + o]; __syncthreads(); }
    float cox = sm[0]; __syncthreads();

    float ef = 0.0f;
    for (int i = tid; i < N_PAT; i += 1024) ef += (float)e[i];
    sm[tid] = ef; __syncthreads();
#pragma unroll
    for (int o = 512; o > 0; o >>= 1) { if (tid < o) sm[tid] += sm[tid + o]; __syncthreads(); }

    if (tid == 0) out[0] = sim - cox / sm[0];
}

// ---------------- launch ----------------
extern "C" void kernel_launch(void* const* d_in, const int* in_sizes, int n_in,
                              void* d_out, int out_size) {
    const float* h   = (const float*)d_in[0];
    const int*   t   = (const int*)d_in[1];
    const int*   e   = (const int*)d_in[2];
    const float* eb0 = (const float*)d_in[3];
    const float* eb1 = (const float*)d_in[4];
    const float* eb2 = (const float*)d_in[5];
    const float* eb3 = (const float*)d_in[6];
    const int*   mg  = (const int*)d_in[7];
    float* out = (float*)d_out;

    cudaFuncSetAttribute(sim_gemm_mma, cudaFuncAttributeMaxDynamicSharedMemorySize, SM_TOTAL);

    prep_kernel<<<(N_PAT * 4 * 32 + 255) / 256, 256>>>(eb0, eb1, eb2, eb3);
    exph_kernel<<<(N_PAT + 255) / 256, 256>>>(h);
    cox_kernel<<<N_PAT / 32, 256>>>(h, t, e);
    sim_gemm_mma<<<NBLK_TRI, 128, SM_TOTAL>>>(mg);
    finish_kernel<<<1, 1024>>>(e, out);
}

// round 5
// speedup vs baseline: 3.9084x; 1.1158x over previous
#include <cuda_runtime.h>
#include <math.h>
#include <stdint.h>

#define N_PAT 4096
#define DIM   256
#define EPSV  1e-8f
#define RBLK  64                 // rows per prep block
#define NRB   (N_PAT / RBLK)     // 64 row-blocks per modality

// ---------------- static scratch ----------------
__device__ float  g_upart[4 * NRB * DIM];   // per (mod,rowblock) partial column sums
__device__ float2 g_vw[4 * NRB];            // per (mod,rowblock) (V,W) partials
__device__ float  g_coxpart[N_PAT];

// ---------------- fused prep: row stats + weighted column partial sums ----------------
// grid = 4 mods * 64 rowblocks; block = 256
__global__ void __launch_bounds__(256)
prep_kernel(const float* __restrict__ eb0, const float* __restrict__ eb1,
            const float* __restrict__ eb2, const float* __restrict__ eb3) {
    __shared__ float inv_s[RBLK];
    __shared__ float snm[8], sw[8];

    int mod = blockIdx.x >> 6;
    int rb  = blockIdx.x & 63;
    int r0  = rb * RBLK;
    const float* base = (mod == 0) ? eb0 : (mod == 1) ? eb1 : (mod == 2) ? eb2 : eb3;

    int tid = threadIdx.x;
    int w = tid >> 5, lane = tid & 31;

    // Phase A: warp w handles rows w*8 .. w*8+7 (one row at a time)
    float nmW = 0.0f, wW = 0.0f;
#pragma unroll
    for (int rr = 0; rr < 8; rr++) {
        int rl = w * 8 + rr;
        const float4* src = (const float4*)(base + (size_t)(r0 + rl) * DIM);
        float4 v0 = src[lane];
        float4 v1 = src[lane + 32];

        float x0 = __shfl_sync(0xffffffffu, v0.x, 0);
        bool eq = (v0.x == x0) && (v0.y == x0) && (v0.z == x0) && (v0.w == x0) &&
                  (v1.x == x0) && (v1.y == x0) && (v1.z == x0) && (v1.w == x0);
        bool miss = (__ballot_sync(0xffffffffu, eq) == 0xffffffffu);

        float ss = v0.x*v0.x + v0.y*v0.y + v0.z*v0.z + v0.w*v0.w
                 + v1.x*v1.x + v1.y*v1.y + v1.z*v1.z + v1.w*v1.w;
#pragma unroll
        for (int o = 16; o > 0; o >>= 1) ss += __shfl_xor_sync(0xffffffffu, ss, o);

        if (lane == 0) {
            float nrm = sqrtf(ss);
            float den = fmaxf(nrm, EPSV);
            inv_s[rl] = miss ? 0.0f : (1.0f / den);
            if (!miss) { nmW += 1.0f; wW += ss / (den * den); }
        }
    }
    if (lane == 0) { snm[w] = nmW; sw[w] = wW; }
    __syncthreads();

    // Phase B: thread 'tid' owns column tid; weighted sum over the 64 rows
    float cs = 0.0f;
    const float* col = base + (size_t)r0 * DIM + tid;
#pragma unroll 8
    for (int r = 0; r < RBLK; r++) cs += inv_s[r] * col[(size_t)r * DIM];
    g_upart[((size_t)blockIdx.x << 8) + tid] = cs;

    if (tid == 0) {
        float V = 0.0f, W = 0.0f;
#pragma unroll
        for (int i = 0; i < 8; i++) { V += snm[i]; W += sw[i]; }
        g_vw[blockIdx.x] = make_float2(V, W);
    }
}

// ---------------- cox: 32 rows per block, fused exp, tiled j ----------------
__global__ void __launch_bounds__(256)
cox_kernel(const float* __restrict__ h, const int* __restrict__ t,
           const int* __restrict__ e) {
    __shared__ int st[1024];
    __shared__ float se[1024];
    int tid = threadIdx.x;
    int il = tid >> 3;
    int sub = tid & 7;
    int i = blockIdx.x * 32 + il;
    int ti = t[i];
    float s = 0.0f;
    for (int j0 = 0; j0 < N_PAT; j0 += 1024) {
        __syncthreads();
        for (int j = tid; j < 1024; j += 256) {
            st[j] = t[j0 + j];
            se[j] = expf(h[j0 + j]);
        }
        __syncthreads();
#pragma unroll 4
        for (int j = sub; j < 1024; j += 8)
            if (ti == 0 || st[j] >= ti) s += se[j];
    }
#pragma unroll
    for (int o = 4; o > 0; o >>= 1) s += __shfl_xor_sync(0xffffffffu, s, o);
    if (sub == 0)
        g_coxpart[i] = e[i] ? (h[i] - logf(s)) : 0.0f;
}

// ---------------- finish: combine everything ----------------
__global__ void __launch_bounds__(256)
finish_kernel(const int* __restrict__ e, const int* __restrict__ mptr,
              float* __restrict__ out) {
    __shared__ float red[256];
    __shared__ float U2s[4];
    int tid = threadIdx.x;

    // per-mod ||u||^2
#pragma unroll
    for (int m = 0; m < 4; m++) {
        float u = 0.0f;
#pragma unroll 8
        for (int rb = 0; rb < NRB; rb++)
            u += g_upart[(((size_t)m * NRB + rb) << 8) + tid];
        red[tid] = u * u;
        __syncthreads();
#pragma unroll
        for (int o = 128; o > 0; o >>= 1) {
            if (tid < o) red[tid] += red[tid + o];
            __syncthreads();
        }
        if (tid == 0) U2s[m] = red[0];
        __syncthreads();
    }

    // cox partial sum
    float cp = 0.0f;
    for (int i = tid; i < N_PAT; i += 256) cp += g_coxpart[i];
    red[tid] = cp;
    __syncthreads();
#pragma unroll
    for (int o = 128; o > 0; o >>= 1) {
        if (tid < o) red[tid] += red[tid + o];
        __syncthreads();
    }
    float coxsum = red[0];
    __syncthreads();

    // sum of events
    float ef = 0.0f;
    for (int i = tid; i < N_PAT; i += 256) ef += (float)e[i];
    red[tid] = ef;
    __syncthreads();
#pragma unroll
    for (int o = 128; o > 0; o >>= 1) {
        if (tid < o) red[tid] += red[tid + o];
        __syncthreads();
    }

    if (tid == 0) {
        int iv = mptr[0];
        float margin = (iv > -1000000 && iv < 1000000) ? (float)iv : __int_as_float(iv);

        double sim = (double)margin * (double)N_PAT * (double)(N_PAT - 1);
#pragma unroll
        for (int m = 0; m < 4; m++) {
            double V = 0.0, W = 0.0;
            for (int rb = 0; rb < NRB; rb++) {
                float2 vw = g_vw[m * NRB + rb];
                V += (double)vw.x;
                W += (double)vw.y;
            }
            sim += W * V - (double)U2s[m];
        }
        double cox = -(double)coxsum / (double)red[0];
        out[0] = (float)(sim + cox);
    }
}

// ---------------- launch ----------------
extern "C" void kernel_launch(void* const* d_in, const int* in_sizes, int n_in,
                              void* d_out, int out_size) {
    const float* h   = (const float*)d_in[0];
    const int*   t   = (const int*)d_in[1];
    const int*   e   = (const int*)d_in[2];
    const float* eb0 = (const float*)d_in[3];
    const float* eb1 = (const float*)d_in[4];
    const float* eb2 = (const float*)d_in[5];
    const float* eb3 = (const float*)d_in[6];
    const int*   mg  = (const int*)d_in[7];
    float* out = (float*)d_out;

    prep_kernel<<<4 * NRB, 256>>>(eb0, eb1, eb2, eb3);
    cox_kernel<<<N_PAT / 32, 256>>>(h, t, e);
    finish_kernel<<<1, 256>>>(e, mg, out);
}

// round 6
// speedup vs baseline: 9.9278x; 2.5401x over previous
#include <cuda_runtime.h>
#include <math.h>
#include <stdint.h>

#define N_PAT 4096
#define DIM   256
#define EPSV  1e-8f
#define RBLK  32                 // rows per prep block
#define NRB   (N_PAT / RBLK)     // 128 row-blocks per modality

// ---------------- static scratch ----------------
__device__ float  g_upart[4 * NRB * DIM];   // per (mod,rowblock) partial column sums
__device__ float2 g_vw[4 * NRB];            // per (mod,rowblock) (V,W) partials
__device__ float  g_coxpart[N_PAT];

// ---------------- fused prep: row stats + weighted column partial sums ----------------
// grid = 4 mods * 128 rowblocks; block = 256
__global__ void __launch_bounds__(256)
prep_kernel(const float* __restrict__ eb0, const float* __restrict__ eb1,
            const float* __restrict__ eb2, const float* __restrict__ eb3) {
    __shared__ float inv_s[RBLK];
    __shared__ float snm[8], sw[8];

    int mod = blockIdx.x >> 7;
    int rb  = blockIdx.x & 127;
    int r0  = rb * RBLK;
    const float* base = (mod == 0) ? eb0 : (mod == 1) ? eb1 : (mod == 2) ? eb2 : eb3;

    int tid = threadIdx.x;
    int w = tid >> 5, lane = tid & 31;

    // Phase A: warp w handles rows w*4 .. w*4+3
    float nmW = 0.0f, wW = 0.0f;
#pragma unroll
    for (int rr = 0; rr < 4; rr++) {
        int rl = w * 4 + rr;
        const float4* src = (const float4*)(base + (size_t)(r0 + rl) * DIM);
        float4 v0 = src[lane];
        float4 v1 = src[lane + 32];

        float x0 = __shfl_sync(0xffffffffu, v0.x, 0);
        bool eq = (v0.x == x0) && (v0.y == x0) && (v0.z == x0) && (v0.w == x0) &&
                  (v1.x == x0) && (v1.y == x0) && (v1.z == x0) && (v1.w == x0);
        bool miss = (__ballot_sync(0xffffffffu, eq) == 0xffffffffu);

        float ss = v0.x*v0.x + v0.y*v0.y + v0.z*v0.z + v0.w*v0.w
                 + v1.x*v1.x + v1.y*v1.y + v1.z*v1.z + v1.w*v1.w;
#pragma unroll
        for (int o = 16; o > 0; o >>= 1) ss += __shfl_xor_sync(0xffffffffu, ss, o);

        if (lane == 0) {
            float nrm = sqrtf(ss);
            float den = fmaxf(nrm, EPSV);
            inv_s[rl] = miss ? 0.0f : (1.0f / den);
            if (!miss) { nmW += 1.0f; wW += ss / (den * den); }
        }
    }
    if (lane == 0) { snm[w] = nmW; sw[w] = wW; }
    __syncthreads();

    // Phase B: thread 'tid' owns column tid; weighted sum over the 32 rows
    float cs = 0.0f;
    const float* col = base + (size_t)r0 * DIM + tid;
#pragma unroll 8
    for (int r = 0; r < RBLK; r++) cs += inv_s[r] * col[(size_t)r * DIM];
    g_upart[((size_t)blockIdx.x << 8) + tid] = cs;

    if (tid == 0) {
        float V = 0.0f, W = 0.0f;
#pragma unroll
        for (int i = 0; i < 8; i++) { V += snm[i]; W += sw[i]; }
        g_vw[blockIdx.x] = make_float2(V, W);
    }
}

// ---------------- cox: 16 rows per block, fused exp, tiled j ----------------
__global__ void __launch_bounds__(256)
cox_kernel(const float* __restrict__ h, const int* __restrict__ t,
           const int* __restrict__ e) {
    __shared__ int st[1024];
    __shared__ float se[1024];
    int tid = threadIdx.x;
    int il = tid >> 4;        // 0..15 local row
    int sub = tid & 15;
    int i = blockIdx.x * 16 + il;
    int ti = t[i];
    float s = 0.0f;
    for (int j0 = 0; j0 < N_PAT; j0 += 1024) {
        __syncthreads();
        for (int j = tid; j < 1024; j += 256) {
            st[j] = t[j0 + j];
            se[j] = expf(h[j0 + j]);
        }
        __syncthreads();
#pragma unroll 8
        for (int j = sub; j < 1024; j += 16)
            if (ti == 0 || st[j] >= ti) s += se[j];
    }
#pragma unroll
    for (int o = 8; o > 0; o >>= 1) s += __shfl_xor_sync(0xffffffffu, s, o);
    if (sub == 0)
        g_coxpart[i] = e[i] ? (h[i] - logf(s)) : 0.0f;
}

// ---------------- finish: fully parallel reductions ----------------
__global__ void __launch_bounds__(1024)
finish_kernel(const int* __restrict__ e, const int* __restrict__ mptr,
              float* __restrict__ out) {
    __shared__ float rv[1024];
    __shared__ float rw[1024];
    __shared__ float U2s[4], sV[4], sW[4];
    int tid = threadIdx.x;

    // 1) per-mod ||u||^2 : thread (mod, col) sums 128 rowblock partials
    {
        int mod = tid >> 8, col = tid & 255;
        float u = 0.0f;
        const float* up = g_upart + (((size_t)mod * NRB) << 8) + col;
#pragma unroll 16
        for (int rb = 0; rb < NRB; rb++) u += up[(size_t)rb << 8];
        rv[tid] = u * u;
    }
    __syncthreads();
#pragma unroll
    for (int o = 128; o > 0; o >>= 1) {
        if ((tid & 255) < o) rv[tid] += rv[tid + o];
        __syncthreads();
    }
    if (tid < 4) U2s[tid] = rv[tid << 8];
    __syncthreads();

    // 2) per-mod V, W : 512 threads load one float2 each
    {
        float V = 0.0f, W = 0.0f;
        if (tid < 4 * NRB) { float2 vw = g_vw[tid]; V = vw.x; W = vw.y; }
        rv[tid] = V; rw[tid] = W;
    }
    __syncthreads();
#pragma unroll
    for (int o = NRB / 2; o > 0; o >>= 1) {
        if (tid < 4 * NRB && (tid & (NRB - 1)) < o) {
            rv[tid] += rv[tid + o];
            rw[tid] += rw[tid + o];
        }
        __syncthreads();
    }
    if (tid < 4) { sV[tid] = rv[tid * NRB]; sW[tid] = rw[tid * NRB]; }
    __syncthreads();

    // 3) cox partial sum + event count
    {
        float cp = 0.0f, ef = 0.0f;
#pragma unroll
        for (int k = 0; k < N_PAT / 1024; k++) {
            int i = tid + k * 1024;
            cp += g_coxpart[i];
            ef += (float)e[i];
        }
        rv[tid] = cp; rw[tid] = ef;
    }
    __syncthreads();
#pragma unroll
    for (int o = 512; o > 0; o >>= 1) {
        if (tid < o) { rv[tid] += rv[tid + o]; rw[tid] += rw[tid + o]; }
        __syncthreads();
    }

    if (tid == 0) {
        int iv = mptr[0];
        float margin = (iv > -1000000 && iv < 1000000) ? (float)iv : __int_as_float(iv);

        double sim = (double)margin * (double)N_PAT * (double)(N_PAT - 1);
#pragma unroll
        for (int m = 0; m < 4; m++)
            sim += (double)sW[m] * (double)sV[m] - (double)U2s[m];
        double cox = -(double)rv[0] / (double)rw[0];
        out[0] = (float)(sim + cox);
    }
}

// ---------------- launch ----------------
extern "C" void kernel_launch(void* const* d_in, const int* in_sizes, int n_in,
                              void* d_out, int out_size) {
    const float* h   = (const float*)d_in[0];
    const int*   t   = (const int*)d_in[1];
    const int*   e   = (const int*)d_in[2];
    const float* eb0 = (const float*)d_in[3];
    const float* eb1 = (const float*)d_in[4];
    const float* eb2 = (const float*)d_in[5];
    const float* eb3 = (const float*)d_in[6];
    const int*   mg  = (const int*)d_in[7];
    float* out = (float*)d_out;

    prep_kernel<<<4 * NRB, 256>>>(eb0, eb1, eb2, eb3);
    cox_kernel<<<N_PAT / 16, 256>>>(h, t, e);
    finish_kernel<<<1, 1024>>>(e, mg, out);
}